// round 12
// baseline (speedup 1.0000x reference)
#include <cuda_runtime.h>
#include <math_constants.h>

// Problem constants
#define BB 64
#define HH 224
#define WW 224
#define CC 196
#define HWP (HH*WW)
#define NEIGH 10

// Register-resident band tiling
#define TFY   36            // rows per thread (interior + 2*KIT halo)
#define KIT   10            // iterations fused per launch
#define BR    16            // interior rows per band (TFY - 2*KIT)
#define BANDS 14            // 224/16 exactly
#define NT    224           // thread = column
#define NW    7             // warps per block
#define NLAB  9             // packed label regs (4 rows each)
#define DYN_SMEM (3 * TFY * NT * (int)sizeof(float))   // scU + scL + swg: 96768 B

// ---------------- static scratch ----------------
__device__ float         g_wg [BB*HWP];
__device__ float         g_cpU[BB*HWP];
__device__ float         g_cpL[BB*HWP];
__device__ float         g_dA [BB*HWP];
__device__ float         g_dB [BB*HWP];
__device__ unsigned char g_lA [BB*HWP];
__device__ unsigned char g_lB [BB*HWP];
__device__ float         g_minval[BB*CC];
__device__ int           g_minidx[BB*CC];
__device__ int           g_centi [BB*CC*2];

// ---------------- Phase 1a: window min + first argmin ----------------
__global__ void minima_kernel(const float* __restrict__ g) {
    int gw   = (blockIdx.x * blockDim.x + threadIdx.x) >> 5;
    int lane = threadIdx.x & 31;
    if (gw >= BB * CC) return;
    int b = gw / CC, c = gw - b * CC;
    int y0 = 8 + 16 * (c / 14);
    int x0 = 8 + 16 * (c % 14);
    int ymin = max(0, y0 - NEIGH), ymax = min(HH, y0 + NEIGH);
    int xmin = max(0, x0 - NEIGH), xmax = min(WW, x0 + NEIGH);
    int ww = xmax - xmin, n = (ymax - ymin) * ww;
    const float* gb = g + (size_t)b * HWP;

    float bv = CUDART_INF_F;
    int   bi = 0x7fffffff;
    for (int k = lane; k < n; k += 32) {
        int ky = k / ww;
        int f = (ymin + ky) * WW + xmin + (k - ky * ww);
        float v = gb[f];
        if (v < bv || (v == bv && f < bi)) { bv = v; bi = f; }
    }
    #pragma unroll
    for (int off = 16; off; off >>= 1) {
        float ov = __shfl_down_sync(0xffffffffu, bv, off);
        int   oi = __shfl_down_sync(0xffffffffu, bi, off);
        if (ov < bv || (ov == bv && oi < bi)) { bv = ov; bi = oi; }
    }
    if (lane == 0) { g_minval[gw] = bv; g_minidx[gw] = bi; }
}

// ---------------- Phase 1b: occupied-dedup, one warp per batch ----------------
__global__ void resolve_kernel(const float* __restrict__ g, float* __restrict__ out_cents) {
    __shared__ unsigned int occ[(HWP + 31) / 32];
    int b    = blockIdx.x;
    int lane = threadIdx.x;
    for (int i = lane; i < (HWP + 31) / 32; i += 32) occ[i] = 0u;
    __syncwarp();
    const float* gb = g + (size_t)b * HWP;

    for (int c = 0; c < CC; c++) {
        float mv = g_minval[b * CC + c];
        int   mi = g_minidx[b * CC + c];
        int y0c = 8 + 16 * (c / 14);
        int x0c = 8 + 16 * (c % 14);
        bool isocc = (occ[mi >> 5] >> (mi & 31)) & 1u;
        int  chosen = mi;
        bool found  = true;
        if (isocc) {
            found = false;
            int ymin = max(0, y0c - NEIGH), ymax = min(HH, y0c + NEIGH);
            int xmin = max(0, x0c - NEIGH), xmax = min(WW, x0c + NEIGH);
            int wwid = xmax - xmin, n = (ymax - ymin) * wwid;
            for (int base = 0; base < n; base += 32) {
                int k = base + lane;
                bool m = false; int f = 0;
                if (k < n) {
                    int ky = k / wwid;
                    f = (ymin + ky) * WW + xmin + (k - ky * wwid);
                    m = (gb[f] == mv) && !((occ[f >> 5] >> (f & 31)) & 1u);
                }
                unsigned bal = __ballot_sync(0xffffffffu, m);
                if (bal) {
                    chosen = __shfl_sync(0xffffffffu, f, __ffs(bal) - 1);
                    found = true;
                    break;
                }
            }
        }
        int cy, cx;
        if (found) {
            if (lane == 0) occ[chosen >> 5] |= 1u << (chosen & 31);
            cy = chosen / WW; cx = chosen - cy * WW;
        } else { cy = y0c; cx = x0c; }
        __syncwarp();
        if (lane == 0) {
            g_centi[(b * CC + c) * 2 + 0] = cy;
            g_centi[(b * CC + c) * 2 + 1] = cx;
            out_cents[(b * CC + c) * 2 + 0] = (float)cy;
            out_cents[(b * CC + c) * 2 + 1] = (float)cx;
        }
    }
}

// ---------------- Phase 2: maps + init (fused) ----------------
__global__ void maps_kernel(const float* __restrict__ xin, const float* __restrict__ g) {
    int i = blockIdx.x * blockDim.x + threadIdx.x;
    if (i >= BB * HWP) return;
    int b = i / HWP;
    int r = i - b * HWP;
    int y = r / WW;
    int x = r - y * WW;

    float gv = g[i];
    float t = gv * gv;
    g_wg[i] = (t * t) * 10.0f;

    const float* cb = xin + (size_t)b * 3 * HWP;
    int yn = (y + 1 == HH) ? 0 : y + 1;
    int xn = (x + 1 == WW) ? 0 : x + 1;
    int rU = yn * WW + x;
    int rL = y * WW + xn;
    float su = 0.0f, sl = 0.0f;
    #pragma unroll
    for (int ch = 0; ch < 3; ch++) {
        float v = cb[ch * HWP + r];
        su += fabsf(v - cb[ch * HWP + rU]);
        sl += fabsf(v - cb[ch * HWP + rL]);
    }
    g_cpU[i] = su * 10.0f;
    g_cpL[i] = sl * 10.0f;

    g_dA[i] = CUDART_INF_F;     // init fused here
    g_lA[i] = 255;
}

// Parallel seed: one thread per (b,c). Collision-free: resolve guarantees
// chosen pixels are unique per batch (occupied bitmap), and fallback positions
// are window centers which no other window (centers >=16 px apart, radius 10)
// can reach.
__global__ void seed_kernel() {
    int i = blockIdx.x * blockDim.x + threadIdx.x;
    if (i >= BB * CC) return;
    int y = g_centi[i * 2 + 0];
    int x = g_centi[i * 2 + 1];
    int b = i / CC;
    int idx = b * HWP + y * WW + x;
    g_dA[idx] = 0.0f;
    g_lA[idx] = (unsigned char)(i - b * CC);
}

// ---------------- packed-label helpers (fold with unrolled q) ----------------
__device__ __forceinline__ unsigned getb(const unsigned* lab, int q) {
    return (lab[q >> 2] >> ((q & 3) * 8)) & 0xFFu;
}
__device__ __forceinline__ void setb(unsigned* lab, int q, unsigned v) {
    int sh = (q & 3) * 8;
    lab[q >> 2] = (lab[q >> 2] & ~(0xFFu << sh)) | (v << sh);
}

// ---------------- Phase 3: KIT fused iterations ----------------
// Thread = column. dist + labels in registers; wg/cpU/cpL tiles in DYNAMIC
// smem (read-only; conflict-free: warp reads fixed row, consecutive cols).
// Vertical passes: pure-register Jacobi (sweep order => neighbor still old).
// Horizontal passes: dist/label neighbor via __shfl, warp boundaries via a
// small static double-buffered smem exchange; cpL[x-1] read directly from
// smem with free toroidal wrap. Exact reference add order (nd+wg)+cp.
template <bool LAST>
__global__ __launch_bounds__(NT, 2) void fused_reg_kernel(int ab, float* __restrict__ out_mask) {
    extern __shared__ float s_dyn[];
    float* scU = s_dyn;                  // [TFY][NT]
    float* scL = s_dyn + TFY * NT;       // [TFY][NT]
    float* swg = s_dyn + 2 * TFY * NT;   // [TFY][NT]

    __shared__ float    sLd[2][NW][TFY];   // lane-0 dist (pre-L)  for L pass
    __shared__ unsigned sLl[2][NW][NLAB];
    __shared__ float    sRd[2][NW][TFY];   // lane-31 dist (post-L) for R pass
    __shared__ unsigned sRl[2][NW][NLAB];

    const float*         din  = ab ? g_dB : g_dA;
    float*               dout = ab ? g_dA : g_dB;
    const unsigned char* lin  = ab ? g_lB : g_lA;
    unsigned char*       lout = ab ? g_lA : g_lB;

    const int x    = threadIdx.x;
    const int lane = x & 31;
    const int wq   = x >> 5;
    const int wqn  = (wq + 1) % NW;        // right neighbor warp (for L)
    const int wqp  = (wq + NW - 1) % NW;   // left neighbor warp (for R)
    const int xl   = (x == 0) ? WW - 1 : x - 1;   // left column (wrapped)
    const int band = blockIdx.x;
    const int b    = blockIdx.y;
    const int bb   = b * HWP;
    const int y0   = band * BR - KIT;

    float    dist[TFY];
    unsigned lab[NLAB];

    // ---- load (coalesced: fixed row, lanes = consecutive columns) ----
    #pragma unroll
    for (int r = 0; r < TFY; r++) {
        int gy = y0 + r; if (gy < 0) gy += HH; else if (gy >= HH) gy -= HH;
        int gi = bb + gy * WW + x;
        dist[r]       = din[gi];
        swg[r*NT + x] = g_wg [gi];
        scU[r*NT + x] = g_cpU[gi];
        scL[r*NT + x] = g_cpL[gi];
        unsigned lv = lin[gi];
        if ((r & 3) == 0) lab[r >> 2] = lv;
        else              lab[r >> 2] |= lv << ((r & 3) * 8);
    }
    // no sync needed yet: the first vertical passes touch only this thread's
    // own smem column (STS->LDS same thread is ordered); the first
    // __syncthreads below publishes the tiles for cross-column reads.

    for (int i = 0; i < KIT; i++) {
        const int pb = i & 1;
        // ---- U: rows [i, TFY-1-i), ascending (reads r+1 old) ----
        #pragma unroll
        for (int r = 0; r < TFY - 1; r++) {
            if (r >= i && r < TFY - 1 - i) {
                float wd = (dist[r + 1] + swg[r*NT + x]) + scU[r*NT + x];
                if (wd < dist[r]) { dist[r] = wd; setb(lab, r, getb(lab, r + 1)); }
            }
        }
        // ---- D: rows [i+1, TFY-1-i), descending (reads r-1 old) ----
        #pragma unroll
        for (int rr = 0; rr < TFY - 2; rr++) {
            int r = TFY - 2 - rr;
            if (r >= i + 1 && r < TFY - 1 - i) {
                float wd = (dist[r - 1] + swg[r*NT + x]) + scU[(r-1)*NT + x];
                if (wd < dist[r]) { dist[r] = wd; setb(lab, r, getb(lab, r - 1)); }
            }
        }

        // ---- L boundary write (pre-L lane-0 state), sync ----
        if (lane == 0) {
            #pragma unroll
            for (int r = 0; r < TFY; r++) sLd[pb][wq][r] = dist[r];
            #pragma unroll
            for (int k = 0; k < NLAB; k++) sLl[pb][wq][k] = lab[k];
        }
        __syncthreads();
        // ---- L: reads column x+1 (old), rows [i+1, TFY-1-i) ----
        {
            unsigned nlab[NLAB];
            #pragma unroll
            for (int k = 0; k < NLAB; k++) {
                nlab[k] = __shfl_down_sync(0xffffffffu, lab[k], 1);
                if (lane == 31) nlab[k] = sLl[pb][wqn][k];
            }
            #pragma unroll
            for (int r = 1; r < TFY - 1; r++) {
                float nd = __shfl_down_sync(0xffffffffu, dist[r], 1);
                if (r >= i + 1 && r < TFY - 1 - i) {
                    if (lane == 31) nd = sLd[pb][wqn][r];
                    float wd = (nd + swg[r*NT + x]) + scL[r*NT + x];
                    if (wd < dist[r]) { dist[r] = wd; setb(lab, r, getb(nlab, r)); }
                }
            }
        }
        // ---- R boundary write (post-L lane-31 state), sync ----
        if (lane == 31) {
            #pragma unroll
            for (int r = 0; r < TFY; r++) sRd[pb][wq][r] = dist[r];
            #pragma unroll
            for (int k = 0; k < NLAB; k++) sRl[pb][wq][k] = lab[k];
        }
        __syncthreads();
        // ---- R: reads column x-1 (post-L), cp = cpL[x-1] via smem ----
        {
            unsigned nlab[NLAB];
            #pragma unroll
            for (int k = 0; k < NLAB; k++) {
                nlab[k] = __shfl_up_sync(0xffffffffu, lab[k], 1);
                if (lane == 0) nlab[k] = sRl[pb][wqp][k];
            }
            #pragma unroll
            for (int r = 1; r < TFY - 1; r++) {
                float nd = __shfl_up_sync(0xffffffffu, dist[r], 1);
                if (r >= i + 1 && r < TFY - 1 - i) {
                    if (lane == 0) nd = sRd[pb][wqp][r];
                    float wd = (nd + swg[r*NT + x]) + scL[r*NT + xl];
                    if (wd < dist[r]) { dist[r] = wd; setb(lab, r, getb(nlab, r)); }
                }
            }
        }
    }

    // ---- store interior rows [KIT, KIT+BR) (BR*BANDS == HH, no clipping) ----
    #pragma unroll
    for (int r = 0; r < BR; r++) {
        int gi = bb + (band * BR + r) * WW + x;
        unsigned v = getb(lab, KIT + r);
        if (LAST) {
            out_mask[gi] = (v == 255u) ? -1.0f : (float)v;
        } else {
            dout[gi] = dist[KIT + r];
            lout[gi] = (unsigned char)v;
        }
    }
}

// ---------------- launch ----------------
extern "C" void kernel_launch(void* const* d_in, const int* in_sizes, int n_in,
                              void* d_out, int out_size) {
    const float* x;
    const float* g;
    if (in_sizes[0] == BB * 3 * HWP) { x = (const float*)d_in[0]; g = (const float*)d_in[1]; }
    else                             { x = (const float*)d_in[1]; g = (const float*)d_in[0]; }

    float* out       = (float*)d_out;
    float* out_cents = out;               // [B, C, 2] float32
    float* out_mask  = out + BB * CC * 2; // [B, H, W] float32

    const int NPX = BB * HWP;
    const int TPB = 256;
    const int GPX = (NPX + TPB - 1) / TPB;

    cudaFuncSetAttribute(fused_reg_kernel<false>,
                         cudaFuncAttributeMaxDynamicSharedMemorySize, DYN_SMEM);
    cudaFuncSetAttribute(fused_reg_kernel<true>,
                         cudaFuncAttributeMaxDynamicSharedMemorySize, DYN_SMEM);

    minima_kernel<<<(BB * CC * 32 + TPB - 1) / TPB, TPB>>>(g);
    resolve_kernel<<<BB, 32>>>(g, out_cents);
    maps_kernel<<<GPX, TPB>>>(x, g);
    seed_kernel<<<(BB * CC + TPB - 1) / TPB, TPB>>>();

    int ab = 0;   // 0: current state in A
    const int NLAUNCH = 50 / KIT;   // 5
    for (int k = 0; k < NLAUNCH - 1; k++) {
        fused_reg_kernel<false><<<dim3(BANDS, BB), NT, DYN_SMEM>>>(ab, out_mask);
        ab ^= 1;
    }
    fused_reg_kernel<true><<<dim3(BANDS, BB), NT, DYN_SMEM>>>(ab, out_mask);
}

// round 13
// speedup vs baseline: 1.5386x; 1.5386x over previous
#include <cuda_runtime.h>
#include <math_constants.h>

// Problem constants
#define BB 64
#define HH 224
#define WW 224
#define CC 196
#define HWP (HH*WW)
#define NEIGH 10

// Split-column band tiling
#define KIT   5             // iterations fused per launch
#define BR    28            // interior rows per band
#define TFY   38            // tile rows = BR + 2*KIT
#define BANDS 8             // 8*28 = 224 exactly
#define RPT   19            // rows per thread (TFY/2)
#define NT    224           // columns (threadIdx.x)
#define NH    2             // halves  (threadIdx.y)
#define NW    7             // warps per half
#define NLAB  5             // packed label regs (4 rows each, 19 rows)
#define DYN_SMEM (3 * TFY * NT * (int)sizeof(float))   // swg+scU+scL: 102144 B

// ---------------- static scratch ----------------
__device__ float         g_wg [BB*HWP];
__device__ float         g_cpU[BB*HWP];
__device__ float         g_cpL[BB*HWP];
__device__ float         g_dA [BB*HWP];
__device__ float         g_dB [BB*HWP];
__device__ unsigned char g_lA [BB*HWP];
__device__ unsigned char g_lB [BB*HWP];
__device__ float         g_minval[BB*CC];
__device__ int           g_minidx[BB*CC];
__device__ int           g_centi [BB*CC*2];

// ---------------- Phase 1a: window min + first argmin ----------------
__global__ void minima_kernel(const float* __restrict__ g) {
    int gw   = (blockIdx.x * blockDim.x + threadIdx.x) >> 5;
    int lane = threadIdx.x & 31;
    if (gw >= BB * CC) return;
    int b = gw / CC, c = gw - b * CC;
    int y0 = 8 + 16 * (c / 14);
    int x0 = 8 + 16 * (c % 14);
    int ymin = max(0, y0 - NEIGH), ymax = min(HH, y0 + NEIGH);
    int xmin = max(0, x0 - NEIGH), xmax = min(WW, x0 + NEIGH);
    int ww = xmax - xmin, n = (ymax - ymin) * ww;
    const float* gb = g + (size_t)b * HWP;

    float bv = CUDART_INF_F;
    int   bi = 0x7fffffff;
    for (int k = lane; k < n; k += 32) {
        int ky = k / ww;
        int f = (ymin + ky) * WW + xmin + (k - ky * ww);
        float v = gb[f];
        if (v < bv || (v == bv && f < bi)) { bv = v; bi = f; }
    }
    #pragma unroll
    for (int off = 16; off; off >>= 1) {
        float ov = __shfl_down_sync(0xffffffffu, bv, off);
        int   oi = __shfl_down_sync(0xffffffffu, bi, off);
        if (ov < bv || (ov == bv && oi < bi)) { bv = ov; bi = oi; }
    }
    if (lane == 0) { g_minval[gw] = bv; g_minidx[gw] = bi; }
}

// ---------------- Phase 1b: occupied-dedup, one warp per batch ----------------
__global__ void resolve_kernel(const float* __restrict__ g, float* __restrict__ out_cents) {
    __shared__ unsigned int occ[(HWP + 31) / 32];
    int b    = blockIdx.x;
    int lane = threadIdx.x;
    for (int i = lane; i < (HWP + 31) / 32; i += 32) occ[i] = 0u;
    __syncwarp();
    const float* gb = g + (size_t)b * HWP;

    for (int c = 0; c < CC; c++) {
        float mv = g_minval[b * CC + c];
        int   mi = g_minidx[b * CC + c];
        int y0c = 8 + 16 * (c / 14);
        int x0c = 8 + 16 * (c % 14);
        bool isocc = (occ[mi >> 5] >> (mi & 31)) & 1u;
        int  chosen = mi;
        bool found  = true;
        if (isocc) {
            found = false;
            int ymin = max(0, y0c - NEIGH), ymax = min(HH, y0c + NEIGH);
            int xmin = max(0, x0c - NEIGH), xmax = min(WW, x0c + NEIGH);
            int wwid = xmax - xmin, n = (ymax - ymin) * wwid;
            for (int base = 0; base < n; base += 32) {
                int k = base + lane;
                bool m = false; int f = 0;
                if (k < n) {
                    int ky = k / wwid;
                    f = (ymin + ky) * WW + xmin + (k - ky * wwid);
                    m = (gb[f] == mv) && !((occ[f >> 5] >> (f & 31)) & 1u);
                }
                unsigned bal = __ballot_sync(0xffffffffu, m);
                if (bal) {
                    chosen = __shfl_sync(0xffffffffu, f, __ffs(bal) - 1);
                    found = true;
                    break;
                }
            }
        }
        int cy, cx;
        if (found) {
            if (lane == 0) occ[chosen >> 5] |= 1u << (chosen & 31);
            cy = chosen / WW; cx = chosen - cy * WW;
        } else { cy = y0c; cx = x0c; }
        __syncwarp();
        if (lane == 0) {
            g_centi[(b * CC + c) * 2 + 0] = cy;
            g_centi[(b * CC + c) * 2 + 1] = cx;
            out_cents[(b * CC + c) * 2 + 0] = (float)cy;
            out_cents[(b * CC + c) * 2 + 1] = (float)cx;
        }
    }
}

// ---------------- Phase 2: maps + init (fused) ----------------
__global__ void maps_kernel(const float* __restrict__ xin, const float* __restrict__ g) {
    int i = blockIdx.x * blockDim.x + threadIdx.x;
    if (i >= BB * HWP) return;
    int b = i / HWP;
    int r = i - b * HWP;
    int y = r / WW;
    int x = r - y * WW;

    float gv = g[i];
    float t = gv * gv;
    g_wg[i] = (t * t) * 10.0f;

    const float* cb = xin + (size_t)b * 3 * HWP;
    int yn = (y + 1 == HH) ? 0 : y + 1;
    int xn = (x + 1 == WW) ? 0 : x + 1;
    int rU = yn * WW + x;
    int rL = y * WW + xn;
    float su = 0.0f, sl = 0.0f;
    #pragma unroll
    for (int ch = 0; ch < 3; ch++) {
        float v = cb[ch * HWP + r];
        su += fabsf(v - cb[ch * HWP + rU]);
        sl += fabsf(v - cb[ch * HWP + rL]);
    }
    g_cpU[i] = su * 10.0f;
    g_cpL[i] = sl * 10.0f;

    g_dA[i] = CUDART_INF_F;     // init fused here
    g_lA[i] = 255;
}

// Parallel seed: one thread per (b,c). Collision-free (see round-9 analysis).
__global__ void seed_kernel() {
    int i = blockIdx.x * blockDim.x + threadIdx.x;
    if (i >= BB * CC) return;
    int y = g_centi[i * 2 + 0];
    int x = g_centi[i * 2 + 1];
    int b = i / CC;
    int idx = b * HWP + y * WW + x;
    g_dA[idx] = 0.0f;
    g_lA[idx] = (unsigned char)(i - b * CC);
}

// ---------------- packed-label helpers ----------------
__device__ __forceinline__ unsigned getb(const unsigned* lab, int q) {
    return (lab[q >> 2] >> ((q & 3) * 8)) & 0xFFu;
}
__device__ __forceinline__ void setb(unsigned* lab, int q, unsigned v) {
    int sh = (q & 3) * 8;
    lab[q >> 2] = (lab[q >> 2] & ~(0xFFu << sh)) | (v << sh);
}

// ---------------- Phase 3: KIT fused iterations, split columns ----------------
// Thread (x,h): column x, rows [h*RPT, h*RPT+RPT) of the TFY-row tile.
// dist+labels in regs; wg/cpU/cpL tiles in dynamic smem. Vertical passes are
// in-place register Jacobi with one seam value exchanged through smem (pre-U
// value from h=1 row 0; post-U value from h=0 row 18). Horizontal passes via
// __shfl within warps (warps are x-contiguous per half) + warp-boundary smem.
// 4 __syncthreads per iteration make all single-buffered exchanges race-free.
// Exact reference add order (nd+wg)+cp throughout.
template <bool LAST>
__global__ void __launch_bounds__(NT*NH, 2) fused_reg_kernel(int ab, float* __restrict__ out_mask) {
    extern __shared__ float s_dyn[];
    float* swg = s_dyn;                  // [TFY][NT]
    float* scU = s_dyn + TFY * NT;       // [TFY][NT]
    float* scL = s_dyn + 2 * TFY * NT;   // [TFY][NT]

    __shared__ float    sLd[NH][NW][RPT];   // lane-0 dist (pre-L)
    __shared__ unsigned sLl[NH][NW][NLAB];
    __shared__ float    sRd[NH][NW][RPT];   // lane-31 dist (post-L)
    __shared__ unsigned sRl[NH][NW][NLAB];
    __shared__ float    seamUd[NT];         // h=1 row0 pre-U dist
    __shared__ unsigned seamUl[NT];
    __shared__ float    seamDd[NT];         // h=0 row18 post-U dist
    __shared__ unsigned seamDl[NT];

    const float*         din  = ab ? g_dB : g_dA;
    float*               dout = ab ? g_dA : g_dB;
    const unsigned char* lin  = ab ? g_lB : g_lA;
    unsigned char*       lout = ab ? g_lA : g_lB;

    const int x    = threadIdx.x;
    const int h    = threadIdx.y;
    const int lane = x & 31;
    const int wq   = x >> 5;
    const int wqn  = (wq + 1) % NW;
    const int wqp  = (wq + NW - 1) % NW;
    const int xl   = (x == 0) ? WW - 1 : x - 1;
    const int band = blockIdx.x;
    const int b    = blockIdx.y;
    const int bb   = b * HWP;
    const int y0   = band * BR - KIT;
    const int tb   = h * RPT;              // this thread's first tile row

    float    dist[RPT];
    unsigned lab[NLAB];

    // ---- load (coalesced) ----
    #pragma unroll
    for (int rl = 0; rl < RPT; rl++) {
        int t  = tb + rl;
        int gy = y0 + t; if (gy < 0) gy += HH; else if (gy >= HH) gy -= HH;
        int gi = bb + gy * WW + x;
        dist[rl]      = din[gi];
        swg[t*NT + x] = g_wg [gi];
        scU[t*NT + x] = g_cpU[gi];
        scL[t*NT + x] = g_cpL[gi];
        unsigned lv = lin[gi];
        if ((rl & 3) == 0) lab[rl >> 2] = lv;
        else               lab[rl >> 2] |= lv << ((rl & 3) * 8);
    }
    // First cross-thread smem reads happen after the first __syncthreads (A).

    for (int i = 0; i < KIT; i++) {
        // ---- seam U write (pre-U h=1 row 0), sync A ----
        if (h == 1) { seamUd[x] = dist[0]; seamUl[x] = getb(lab, 0); }
        __syncthreads();

        // ---- U: update tile rows [i, TFY-1-i), ascending, in place ----
        if (h == 0) {
            #pragma unroll
            for (int rl = 0; rl < RPT; rl++) {   // t = rl, window rl >= i
                if (rl >= i) {
                    float nd; unsigned nl;
                    if (rl < RPT - 1) { nd = dist[rl + 1]; nl = getb(lab, rl + 1); }
                    else              { nd = seamUd[x];    nl = seamUl[x]; }
                    float wd = (nd + swg[rl*NT + x]) + scU[rl*NT + x];
                    if (wd < dist[rl]) { dist[rl] = wd; setb(lab, rl, nl); }
                }
            }
        } else {
            #pragma unroll
            for (int rl = 0; rl < RPT - 1; rl++) {  // t = RPT+rl, window rl < RPT-1-i
                if (rl < RPT - 1 - i) {
                    int t = RPT + rl;
                    float wd = (dist[rl + 1] + swg[t*NT + x]) + scU[t*NT + x];
                    if (wd < dist[rl]) { dist[rl] = wd; setb(lab, rl, getb(lab, rl + 1)); }
                }
            }
        }

        // ---- seam D write (post-U h=0 row RPT-1), sync B ----
        if (h == 0) { seamDd[x] = dist[RPT - 1]; seamDl[x] = getb(lab, RPT - 1); }
        __syncthreads();

        // ---- D: update tile rows [i+1, TFY-1-i), descending, in place ----
        if (h == 0) {
            #pragma unroll
            for (int rr = 0; rr < RPT - 1; rr++) {
                int rl = RPT - 1 - rr;            // t = rl, window rl >= i+1
                if (rl >= i + 1) {
                    float wd = (dist[rl - 1] + swg[rl*NT + x]) + scU[(rl-1)*NT + x];
                    if (wd < dist[rl]) { dist[rl] = wd; setb(lab, rl, getb(lab, rl - 1)); }
                }
            }
        } else {
            #pragma unroll
            for (int rr = 0; rr < RPT; rr++) {
                int rl = RPT - 1 - rr;            // t = RPT+rl, window rl < RPT-1-i
                if (rl < RPT - 1 - i) {
                    int t = RPT + rl;
                    float nd; unsigned nl;
                    if (rl > 0) { nd = dist[rl - 1]; nl = getb(lab, rl - 1); }
                    else        { nd = seamDd[x];    nl = seamDl[x]; }
                    float wd = (nd + swg[t*NT + x]) + scU[(t-1)*NT + x];
                    if (wd < dist[rl]) { dist[rl] = wd; setb(lab, rl, nl); }
                }
            }
        }

        // ---- L boundary write (pre-L lane-0 state), sync C ----
        if (lane == 0) {
            #pragma unroll
            for (int rl = 0; rl < RPT; rl++) sLd[h][wq][rl] = dist[rl];
            #pragma unroll
            for (int k = 0; k < NLAB; k++)   sLl[h][wq][k] = lab[k];
        }
        __syncthreads();
        // ---- L: reads column x+1 (old), tile rows [i+1, TFY-1-i) ----
        {
            unsigned nlab[NLAB];
            #pragma unroll
            for (int k = 0; k < NLAB; k++) {
                nlab[k] = __shfl_down_sync(0xffffffffu, lab[k], 1);
                if (lane == 31) nlab[k] = sLl[h][wqn][k];
            }
            #pragma unroll
            for (int rl = 0; rl < RPT; rl++) {
                float nd = __shfl_down_sync(0xffffffffu, dist[rl], 1);
                bool act = (h == 0) ? (rl >= i + 1) : (rl < RPT - 1 - i);
                if (act) {
                    if (lane == 31) nd = sLd[h][wqn][rl];
                    int t = tb + rl;
                    float wd = (nd + swg[t*NT + x]) + scL[t*NT + x];
                    if (wd < dist[rl]) { dist[rl] = wd; setb(lab, rl, getb(nlab, rl)); }
                }
            }
        }
        // ---- R boundary write (post-L lane-31 state), sync D ----
        if (lane == 31) {
            #pragma unroll
            for (int rl = 0; rl < RPT; rl++) sRd[h][wq][rl] = dist[rl];
            #pragma unroll
            for (int k = 0; k < NLAB; k++)   sRl[h][wq][k] = lab[k];
        }
        __syncthreads();
        // ---- R: reads column x-1 (post-L), cp = cpL[x-1] via smem ----
        {
            unsigned nlab[NLAB];
            #pragma unroll
            for (int k = 0; k < NLAB; k++) {
                nlab[k] = __shfl_up_sync(0xffffffffu, lab[k], 1);
                if (lane == 0) nlab[k] = sRl[h][wqp][k];
            }
            #pragma unroll
            for (int rl = 0; rl < RPT; rl++) {
                float nd = __shfl_up_sync(0xffffffffu, dist[rl], 1);
                bool act = (h == 0) ? (rl >= i + 1) : (rl < RPT - 1 - i);
                if (act) {
                    if (lane == 0) nd = sRd[h][wqp][rl];
                    int t = tb + rl;
                    float wd = (nd + swg[t*NT + x]) + scL[t*NT + xl];
                    if (wd < dist[rl]) { dist[rl] = wd; setb(lab, rl, getb(nlab, rl)); }
                }
            }
        }
    }

    // ---- store interior tile rows [KIT, KIT+BR): h=0 -> rl in [KIT,RPT),
    //      h=1 -> rl in [0, BR-(RPT-KIT)) ----
    if (h == 0) {
        #pragma unroll
        for (int rl = KIT; rl < RPT; rl++) {
            int gi = bb + (band * BR + rl - KIT) * WW + x;
            unsigned v = getb(lab, rl);
            if (LAST) out_mask[gi] = (v == 255u) ? -1.0f : (float)v;
            else      { dout[gi] = dist[rl]; lout[gi] = (unsigned char)v; }
        }
    } else {
        #pragma unroll
        for (int rl = 0; rl < BR - (RPT - KIT); rl++) {
            int gi = bb + (band * BR + (RPT - KIT) + rl) * WW + x;
            unsigned v = getb(lab, rl);
            if (LAST) out_mask[gi] = (v == 255u) ? -1.0f : (float)v;
            else      { dout[gi] = dist[rl]; lout[gi] = (unsigned char)v; }
        }
    }
}

// ---------------- launch ----------------
extern "C" void kernel_launch(void* const* d_in, const int* in_sizes, int n_in,
                              void* d_out, int out_size) {
    const float* x;
    const float* g;
    if (in_sizes[0] == BB * 3 * HWP) { x = (const float*)d_in[0]; g = (const float*)d_in[1]; }
    else                             { x = (const float*)d_in[1]; g = (const float*)d_in[0]; }

    float* out       = (float*)d_out;
    float* out_cents = out;               // [B, C, 2] float32
    float* out_mask  = out + BB * CC * 2; // [B, H, W] float32

    const int NPX = BB * HWP;
    const int TPB = 256;
    const int GPX = (NPX + TPB - 1) / TPB;

    cudaFuncSetAttribute(fused_reg_kernel<false>,
                         cudaFuncAttributeMaxDynamicSharedMemorySize, DYN_SMEM);
    cudaFuncSetAttribute(fused_reg_kernel<true>,
                         cudaFuncAttributeMaxDynamicSharedMemorySize, DYN_SMEM);

    minima_kernel<<<(BB * CC * 32 + TPB - 1) / TPB, TPB>>>(g);
    resolve_kernel<<<BB, 32>>>(g, out_cents);
    maps_kernel<<<GPX, TPB>>>(x, g);
    seed_kernel<<<(BB * CC + TPB - 1) / TPB, TPB>>>();

    dim3 blk(NT, NH);
    int ab = 0;   // 0: current state in A
    const int NLAUNCH = 50 / KIT;   // 10
    for (int k = 0; k < NLAUNCH - 1; k++) {
        fused_reg_kernel<false><<<dim3(BANDS, BB), blk, DYN_SMEM>>>(ab, out_mask);
        ab ^= 1;
    }
    fused_reg_kernel<true><<<dim3(BANDS, BB), blk, DYN_SMEM>>>(ab, out_mask);
}